// round 14
// baseline (speedup 1.0000x reference)
#include <cuda_runtime.h>
#include <cstdint>

#define BATCH 64
#define NSPEC 8
#define VOCAB 128000
#define ROWS (BATCH * NSPEC)                 // 512
#define SEGS_PER_ROW 2
#define NCTAS (ROWS * SEGS_PER_ROW)          // 1024
#define NTHREADS 128
#define VEC_PER_SEG (VOCAB / 4 / SEGS_PER_ROW)   // 16000
#define UNROLL 5
#define STRIDE NTHREADS
#define BLOCKS_TOTAL 25                      // 25*5*128 = 16000
#define BLOCKS_STATIC 20                     // static bulk (80%)
#define BLOCKS_STEAL (BLOCKS_TOTAL - BLOCKS_STATIC)  // 5 per stolen unit
#define NSTEAL NCTAS                         // 1024 stolen units
#define STEAL_BASE (BLOCKS_STATIC * UNROLL * STRIDE) // vec offset 12800

// Scratch (device globals; zero at load, re-zeroed each call by epilogue).
__device__ unsigned long long g_row[ROWS];   // packed (ford(v)<<32 | ~idx)
__device__ unsigned g_ticket;
__device__ unsigned g_count;

__device__ __forceinline__ unsigned ford(float f) {
    unsigned u = __float_as_uint(f);
    return u ^ ((unsigned)((int)u >> 31) | 0x80000000u);
}
__device__ __forceinline__ float max4(float4 v) {
    return fmaxf(fmaxf(v.x, v.y), fmaxf(v.z, v.w));
}

// Double-buffered 5-block scan over [seg_base, seg_base + nblocks*5*128).
__device__ __forceinline__ void scan_blocks(const float4* __restrict__ p,
                                            int seg_base, int nblocks,
                                            float& best, int& kbest) {
    best = -3.402823466e+38f;
    int kcur = seg_base + threadIdx.x;
    kbest = kcur;
    float4 v0 = __ldcs(&p[kcur]);
    float4 v1 = __ldcs(&p[kcur + STRIDE]);
    float4 v2 = __ldcs(&p[kcur + 2 * STRIDE]);
    float4 v3 = __ldcs(&p[kcur + 3 * STRIDE]);
    float4 v4 = __ldcs(&p[kcur + 4 * STRIDE]);
#pragma unroll 1
    for (int it = 0; it < nblocks - 1; ++it) {
        const int knext = kcur + UNROLL * STRIDE;
        float4 w0 = __ldcs(&p[knext]);
        float4 w1 = __ldcs(&p[knext + STRIDE]);
        float4 w2 = __ldcs(&p[knext + 2 * STRIDE]);
        float4 w3 = __ldcs(&p[knext + 3 * STRIDE]);
        float4 w4 = __ldcs(&p[knext + 4 * STRIDE]);
        float bm = fmaxf(fmaxf(fmaxf(max4(v0), max4(v1)),
                               fmaxf(max4(v2), max4(v3))), max4(v4));
        if (bm > best) { best = bm; kbest = kcur; }  // strict >: earliest
        v0 = w0; v1 = w1; v2 = w2; v3 = w3; v4 = w4;
        kcur = knext;
    }
    float bm = fmaxf(fmaxf(fmaxf(max4(v0), max4(v1)),
                           fmaxf(max4(v2), max4(v3))), max4(v4));
    if (bm > best) { best = bm; kbest = kcur; }
}

// Re-read winning block for exact earliest index, then CTA-reduce the packed
// key and fold into g_row[row]. s_key is reused across calls (post-sync).
__device__ __forceinline__ void reduce_and_commit(
        const float4* __restrict__ p, float best, int kbest, int row,
        unsigned long long* s_key) {
    int bidx = 0;
    bool f = false;
#pragma unroll
    for (int u = 0; u < UNROLL; ++u) {
        float4 v = p[kbest + u * STRIDE];
        int base = (kbest + u * STRIDE) * 4;
        if (!f && v.x == best) { bidx = base;     f = true; }
        if (!f && v.y == best) { bidx = base + 1; f = true; }
        if (!f && v.z == best) { bidx = base + 2; f = true; }
        if (!f && v.w == best) { bidx = base + 3; f = true; }
    }
    unsigned long long key =
        ((unsigned long long)ford(best) << 32) |
        (unsigned long long)(0xFFFFFFFFu - (unsigned)bidx);
#pragma unroll
    for (int off = 16; off > 0; off >>= 1) {
        unsigned long long o = __shfl_down_sync(0xFFFFFFFFu, key, off);
        key = (o > key) ? o : key;
    }
    if ((threadIdx.x & 31) == 0) s_key[threadIdx.x >> 5] = key;
    __syncthreads();
    if (threadIdx.x == 0) {
        key = s_key[0];
#pragma unroll
        for (int w = 1; w < NTHREADS / 32; ++w)
            key = (s_key[w] > key) ? s_key[w] : key;
        atomicMax(&g_row[row], key);
    }
    __syncthreads();   // s_key reusable after this
}

__global__ void __launch_bounds__(NTHREADS, 8)
fused_kernel(const float* __restrict__ logits,
             const void* __restrict__ draft_raw,
             const void* __restrict__ bonus_raw,
             float* __restrict__ out) {
    const float4* __restrict__ vec = reinterpret_cast<const float4*>(logits);
    __shared__ unsigned long long s_key[NTHREADS / 32];
    __shared__ unsigned s_t;
    __shared__ int s_last, s_not64;

    // ---- static bulk: blocks 0..19 of this CTA's (row, seg) ----
    const int row = blockIdx.x >> 1;
    const int seg = blockIdx.x & 1;
    {
        const float4* __restrict__ p = vec + (size_t)row * (VOCAB / 4);
        float best; int kbest;
        scan_blocks(p, seg * VEC_PER_SEG, BLOCKS_STATIC, best, kbest);
        reduce_and_commit(p, best, kbest, row, s_key);
    }

    // ---- stolen tail: 1024 units of 5 blocks (last 20% of every segment) ----
    for (;;) {
        if (threadIdx.x == 0) s_t = atomicAdd(&g_ticket, 1u);
        __syncthreads();
        const unsigned t = s_t;
        if (t >= NSTEAL) break;
        const int urow = t >> 1;
        const int useg = t & 1;
        const float4* __restrict__ p = vec + (size_t)urow * (VOCAB / 4);
        float best; int kbest;
        scan_blocks(p, useg * VEC_PER_SEG + STEAL_BASE, BLOCKS_STEAL,
                    best, kbest);
        reduce_and_commit(p, best, kbest, urow, s_key);
    }

    // ---- last-CTA-done handshake ----
    if (threadIdx.x == 0) {
        __threadfence();
        unsigned c = atomicAdd(&g_count, 1u);
        s_last = (c == (unsigned)(gridDim.x - 1));
        s_not64 = 0;
    }
    __syncthreads();
    if (!s_last) return;
    __threadfence();                           // acquire all atomicMax

    // ---- rejection-sampling epilogue ----
    // Runtime input dtype detect: first 2048 B of draft exist under either
    // dtype; int64 => every high word is 0 (tokens < 128000).
    const unsigned long long* d64chk = (const unsigned long long*)draft_raw;
    for (int j = threadIdx.x; j < 256; j += NTHREADS)
        if (d64chk[j] >> 32) atomicOr(&s_not64, 1);
    __syncthreads();
    const bool is64 = (s_not64 == 0);

    const int b = threadIdx.x;
    if (b < BATCH) {
        const long long* draft64 = (const long long*)draft_raw;
        const int*       draft32 = (const int*)draft_raw;
        const long long* bonus64 = (const long long*)bonus_raw;
        const int*       bonus32 = (const int*)bonus_raw;
        const volatile unsigned long long* vrow =
            (const volatile unsigned long long*)g_row;

        int tgt[NSPEC];
        bool eq[NSPEC];
        int cum = 0;
#pragma unroll
        for (int s = 0; s < NSPEC; ++s) {
            unsigned long long km = vrow[b * NSPEC + s];
            tgt[s] = (int)(0xFFFFFFFFu - (unsigned)(km & 0xFFFFFFFFull));
            long long dv = is64 ? draft64[b * NSPEC + s]
                                : (long long)draft32[b * NSPEC + s];
            cum += (dv == (long long)tgt[s]) ? 1 : 0;
            eq[s] = ((cum - 1) == s);          // drafts 0..s all matched
        }

        int sum_eq = 0;
#pragma unroll
        for (int s = 0; s < NSPEC; ++s) sum_eq += eq[s] ? 1 : 0;
        const int num_rejected = NSPEC - sum_eq;

        int first_diff = 0;                    // jnp.argmin: 1st False else 0
        bool any_false = false;
#pragma unroll
        for (int s = 0; s < NSPEC; ++s)
            if (!any_false && !eq[s]) { first_diff = s; any_false = true; }

        float outrow[NSPEC + 1];
        int keep_count = 0;
#pragma unroll
        for (int s = 0; s < NSPEC; ++s) {
            bool keep = (s <= first_diff) || eq[s];
            outrow[s] = keep ? (float)tgt[s] : -1.0f;
            keep_count += keep ? 1 : 0;
        }
        const bool last_all = eq[NSPEC - 1];
        long long bonus = is64 ? bonus64[b] : (long long)bonus32[b];
        outrow[NSPEC] = last_all ? (float)bonus : -1.0f;
        keep_count += last_all ? 1 : 0;

        const float last_tok = outrow[keep_count - 1];

        // Flattened tuple: [64*9 tokens | 64 num_rejected | 64 last_token]
#pragma unroll
        for (int s = 0; s <= NSPEC; ++s)
            out[b * (NSPEC + 1) + s] = outrow[s];
        out[BATCH * (NSPEC + 1) + b]         = (float)num_rejected;
        out[BATCH * (NSPEC + 1) + BATCH + b] = last_tok;
    }

    __syncthreads();
    // Reset scratch for next graph replay.
    for (int i = threadIdx.x; i < ROWS; i += NTHREADS) g_row[i] = 0ull;
    if (threadIdx.x == 0) { g_ticket = 0u; g_count = 0u; }
}

extern "C" void kernel_launch(void* const* d_in, const int* in_sizes, int n_in,
                              void* d_out, int out_size) {
    const float* logits = (const float*)d_in[0];   // [64, 8, 128000] fp32
    const void*  draft  = d_in[1];                 // [64, 8] int64 or int32
    const void*  bonus  = d_in[2];                 // [64, 1] int64 or int32
    (void)in_sizes; (void)n_in; (void)out_size;

    fused_kernel<<<NCTAS, NTHREADS>>>(logits, draft, bonus, (float*)d_out);
}

// round 15
// speedup vs baseline: 1.1471x; 1.1471x over previous
#include <cuda_runtime.h>
#include <cstdint>

#define BATCH 64
#define NSPEC 8
#define VOCAB 128000
#define ROWS (BATCH * NSPEC)
#define SEGS_PER_ROW 2
#define NPART (ROWS * SEGS_PER_ROW)        // 1024 partials
#define NTHREADS 128
#define VEC_PER_SEG (VOCAB / 4 / SEGS_PER_ROW)   // 16000
#define UNROLL 5
#define BLOCKS_PER_THREAD 25               // 25 * 5 * 128 = 16000 exact
#define STRIDE NTHREADS

// Scratch (device globals, allocation-free).
__device__ unsigned long long g_part[NPART];
__device__ unsigned g_count;

// Monotone order-preserving fp32 -> u32 (no NaNs in input).
__device__ __forceinline__ unsigned ford(float f) {
    unsigned u = __float_as_uint(f);
    return u ^ ((unsigned)((int)u >> 31) | 0x80000000u);
}

__device__ __forceinline__ float max4(float4 v) {
    return fmaxf(fmaxf(v.x, v.y), fmaxf(v.z, v.w));
}

// 1024 CTAs: (row, half-row segment) partial argmax + last-CTA epilogue.
// Final configuration (R8): static assignment, double-buffered 5-block
// pipeline (10 LDG.128 .cs in flight), measured at the DRAM stream ceiling
// (6.35 TB/s = 79% of spec). All scheduling alternatives (SW stealing, HW
// distributor, hybrid, L2 residency) measured slower in R10-R14.
__global__ void __launch_bounds__(NTHREADS, 8)
fused_kernel(const float* __restrict__ logits,
             const void* __restrict__ draft_raw,
             const void* __restrict__ bonus_raw,
             float* __restrict__ out) {
    const int row = blockIdx.x >> 1;
    const int seg = blockIdx.x & 1;
    const float4* __restrict__ p =
        reinterpret_cast<const float4*>(logits + (size_t)row * VOCAB);
    const int seg_base = seg * VEC_PER_SEG;

    // ---- software-pipelined streaming block-max (10 LDG.128 in flight) ----
    float best = -3.402823466e+38f;
    int kbest = seg_base + threadIdx.x;
    int kcur = seg_base + threadIdx.x;

    float4 v0 = __ldcs(&p[kcur]);
    float4 v1 = __ldcs(&p[kcur + STRIDE]);
    float4 v2 = __ldcs(&p[kcur + 2 * STRIDE]);
    float4 v3 = __ldcs(&p[kcur + 3 * STRIDE]);
    float4 v4 = __ldcs(&p[kcur + 4 * STRIDE]);

#pragma unroll 1
    for (int it = 0; it < BLOCKS_PER_THREAD - 1; ++it) {
        const int knext = kcur + UNROLL * STRIDE;
        // prefetch next block (front-batched, overlaps the tree below)
        float4 w0 = __ldcs(&p[knext]);
        float4 w1 = __ldcs(&p[knext + STRIDE]);
        float4 w2 = __ldcs(&p[knext + 2 * STRIDE]);
        float4 w3 = __ldcs(&p[knext + 3 * STRIDE]);
        float4 w4 = __ldcs(&p[knext + 4 * STRIDE]);
        float bm = fmaxf(fmaxf(fmaxf(max4(v0), max4(v1)),
                               fmaxf(max4(v2), max4(v3))), max4(v4));
        if (bm > best) { best = bm; kbest = kcur; }  // strict >: earliest block
        v0 = w0; v1 = w1; v2 = w2; v3 = w3; v4 = w4;
        kcur = knext;
    }
    {   // peeled last block
        float bm = fmaxf(fmaxf(fmaxf(max4(v0), max4(v1)),
                               fmaxf(max4(v2), max4(v3))), max4(v4));
        if (bm > best) { best = bm; kbest = kcur; }
    }

    // Recover exact element index: re-read winning block, first match wins.
    int bidx = 0;
    bool found = false;
#pragma unroll
    for (int u = 0; u < UNROLL; ++u) {
        float4 v = p[kbest + u * STRIDE];
        int base = (kbest + u * STRIDE) * 4;
        if (!found && v.x == best) { bidx = base;     found = true; }
        if (!found && v.y == best) { bidx = base + 1; found = true; }
        if (!found && v.z == best) { bidx = base + 2; found = true; }
        if (!found && v.w == best) { bidx = base + 3; found = true; }
    }

    // Pack (value, ~idx): u64 max == (max value, then smallest row index).
    unsigned long long key =
        ((unsigned long long)ford(best) << 32) |
        (unsigned long long)(0xFFFFFFFFu - (unsigned)bidx);

#pragma unroll
    for (int off = 16; off > 0; off >>= 1) {
        unsigned long long o = __shfl_down_sync(0xFFFFFFFFu, key, off);
        key = (o > key) ? o : key;
    }
    __shared__ unsigned long long s_key[NTHREADS / 32];
    __shared__ int s_last;
    __shared__ int s_not64;
    if ((threadIdx.x & 31) == 0) s_key[threadIdx.x >> 5] = key;
    __syncthreads();
    if (threadIdx.x == 0) {
        key = s_key[0];
#pragma unroll
        for (int w = 1; w < NTHREADS / 32; ++w)
            key = (s_key[w] > key) ? s_key[w] : key;
        g_part[blockIdx.x] = key;
        __threadfence();                        // release partial
        unsigned t = atomicAdd(&g_count, 1u);
        s_last = (t == (unsigned)(gridDim.x - 1));
        s_not64 = 0;
    }
    __syncthreads();
    if (!s_last) return;
    __threadfence();                            // acquire all partials

    // ---- rejection-sampling epilogue ----
    // Runtime input dtype detect: first 2048 B of draft exist under either
    // dtype; int64 => every high word is 0 (tokens < 128000).
    const unsigned long long* d64chk = (const unsigned long long*)draft_raw;
    for (int j = threadIdx.x; j < 256; j += NTHREADS)
        if (d64chk[j] >> 32) atomicOr(&s_not64, 1);
    __syncthreads();
    const bool is64 = (s_not64 == 0);

    const int b = threadIdx.x;
    if (b < BATCH) {
        const long long* draft64 = (const long long*)draft_raw;
        const int*       draft32 = (const int*)draft_raw;
        const long long* bonus64 = (const long long*)bonus_raw;
        const int*       bonus32 = (const int*)bonus_raw;

        int tgt[NSPEC];
        bool eq[NSPEC];
        int cum = 0;
#pragma unroll
        for (int s = 0; s < NSPEC; ++s) {
            const int r = b * NSPEC + s;
            unsigned long long k0 = g_part[2 * r];
            unsigned long long k1 = g_part[2 * r + 1];
            unsigned long long km = (k1 > k0) ? k1 : k0;
            tgt[s] = (int)(0xFFFFFFFFu - (unsigned)(km & 0xFFFFFFFFull));
            long long dv = is64 ? draft64[r] : (long long)draft32[r];
            cum += (dv == (long long)tgt[s]) ? 1 : 0;
            eq[s] = ((cum - 1) == s);           // drafts 0..s all matched
        }

        int sum_eq = 0;
#pragma unroll
        for (int s = 0; s < NSPEC; ++s) sum_eq += eq[s] ? 1 : 0;
        const int num_rejected = NSPEC - sum_eq;

        int first_diff = 0;                     // jnp.argmin: first False else 0
        bool any_false = false;
#pragma unroll
        for (int s = 0; s < NSPEC; ++s)
            if (!any_false && !eq[s]) { first_diff = s; any_false = true; }

        float outrow[NSPEC + 1];
        int keep_count = 0;
#pragma unroll
        for (int s = 0; s < NSPEC; ++s) {
            bool keep = (s <= first_diff) || eq[s];
            outrow[s] = keep ? (float)tgt[s] : -1.0f;
            keep_count += keep ? 1 : 0;
        }
        const bool last_all = eq[NSPEC - 1];
        long long bonus = is64 ? bonus64[b] : (long long)bonus32[b];
        outrow[NSPEC] = last_all ? (float)bonus : -1.0f;
        keep_count += last_all ? 1 : 0;

        const float last_tok = outrow[keep_count - 1];

        // Flattened tuple: [64*9 tokens | 64 num_rejected | 64 last_token]
#pragma unroll
        for (int s = 0; s <= NSPEC; ++s)
            out[b * (NSPEC + 1) + s] = outrow[s];
        out[BATCH * (NSPEC + 1) + b]         = (float)num_rejected;
        out[BATCH * (NSPEC + 1) + BATCH + b] = last_tok;
    }

    __syncthreads();
    if (threadIdx.x == 0) g_count = 0;          // reset for next graph replay
}

extern "C" void kernel_launch(void* const* d_in, const int* in_sizes, int n_in,
                              void* d_out, int out_size) {
    const float* logits = (const float*)d_in[0];   // [64, 8, 128000] fp32
    const void*  draft  = d_in[1];                 // [64, 8] int64 or int32
    const void*  bonus  = d_in[2];                 // [64, 1] int64 or int32
    (void)in_sizes; (void)n_in; (void)out_size;

    fused_kernel<<<NPART, NTHREADS>>>(logits, draft, bonus, (float*)d_out);
}

// round 17
// speedup vs baseline: 1.2037x; 1.0494x over previous
#include <cuda_runtime.h>
#include <cstdint>

#define BATCH 64
#define NSPEC 8
#define VOCAB 128000
#define ROWS (BATCH * NSPEC)
#define SEGS_PER_ROW 2
#define NPART (ROWS * SEGS_PER_ROW)        // 1024 partials
#define NTHREADS 128
#define VEC_PER_SEG (VOCAB / 4 / SEGS_PER_ROW)   // 16000
#define UNROLL 5
#define BLOCKS_PER_THREAD 25               // 25 * 5 * 128 = 16000 exact
#define STRIDE NTHREADS

// Scratch (device globals, allocation-free).
__device__ unsigned long long g_part[NPART];
__device__ unsigned g_count;

// Monotone order-preserving fp32 -> u32 (no NaNs in input).
__device__ __forceinline__ unsigned ford(float f) {
    unsigned u = __float_as_uint(f);
    return u ^ ((unsigned)((int)u >> 31) | 0x80000000u);
}

__device__ __forceinline__ float max4(float4 v) {
    return fmaxf(fmaxf(v.x, v.y), fmaxf(v.z, v.w));
}

// FINAL (R8 configuration, verified twice: 41.3 / 43.5 us, noise band +-2us).
// 1024 CTAs x 128 threads, one (row, half-row-segment) each; double-buffered
// 5x LDG.128 .cs pipeline (10 loads in flight) at the measured DRAM stream
// ceiling (~6.2-6.35 TB/s = 77-79% of 8 TB/s spec). Alternatives measured
// and rejected: no-.cs (51.6), L2-residency split (47.9), SW work-stealing
// (49.7), HW-distributor tiny CTAs (47.3), hybrid static+steal (49.9).
__global__ void __launch_bounds__(NTHREADS, 8)
fused_kernel(const float* __restrict__ logits,
             const void* __restrict__ draft_raw,
             const void* __restrict__ bonus_raw,
             float* __restrict__ out) {
    const int row = blockIdx.x >> 1;
    const int seg = blockIdx.x & 1;
    const float4* __restrict__ p =
        reinterpret_cast<const float4*>(logits + (size_t)row * VOCAB);
    const int seg_base = seg * VEC_PER_SEG;

    // ---- software-pipelined streaming block-max (10 LDG.128 in flight) ----
    float best = -3.402823466e+38f;
    int kbest = seg_base + threadIdx.x;
    int kcur = seg_base + threadIdx.x;

    float4 v0 = __ldcs(&p[kcur]);
    float4 v1 = __ldcs(&p[kcur + STRIDE]);
    float4 v2 = __ldcs(&p[kcur + 2 * STRIDE]);
    float4 v3 = __ldcs(&p[kcur + 3 * STRIDE]);
    float4 v4 = __ldcs(&p[kcur + 4 * STRIDE]);

#pragma unroll 1
    for (int it = 0; it < BLOCKS_PER_THREAD - 1; ++it) {
        const int knext = kcur + UNROLL * STRIDE;
        // prefetch next block (front-batched, overlaps the tree below)
        float4 w0 = __ldcs(&p[knext]);
        float4 w1 = __ldcs(&p[knext + STRIDE]);
        float4 w2 = __ldcs(&p[knext + 2 * STRIDE]);
        float4 w3 = __ldcs(&p[knext + 3 * STRIDE]);
        float4 w4 = __ldcs(&p[knext + 4 * STRIDE]);
        float bm = fmaxf(fmaxf(fmaxf(max4(v0), max4(v1)),
                               fmaxf(max4(v2), max4(v3))), max4(v4));
        if (bm > best) { best = bm; kbest = kcur; }  // strict >: earliest block
        v0 = w0; v1 = w1; v2 = w2; v3 = w3; v4 = w4;
        kcur = knext;
    }
    {   // peeled last block
        float bm = fmaxf(fmaxf(fmaxf(max4(v0), max4(v1)),
                               fmaxf(max4(v2), max4(v3))), max4(v4));
        if (bm > best) { best = bm; kbest = kcur; }
    }

    // Recover exact element index: re-read winning block, first match wins.
    int bidx = 0;
    bool found = false;
#pragma unroll
    for (int u = 0; u < UNROLL; ++u) {
        float4 v = p[kbest + u * STRIDE];
        int base = (kbest + u * STRIDE) * 4;
        if (!found && v.x == best) { bidx = base;     found = true; }
        if (!found && v.y == best) { bidx = base + 1; found = true; }
        if (!found && v.z == best) { bidx = base + 2; found = true; }
        if (!found && v.w == best) { bidx = base + 3; found = true; }
    }

    // Pack (value, ~idx): u64 max == (max value, then smallest row index).
    unsigned long long key =
        ((unsigned long long)ford(best) << 32) |
        (unsigned long long)(0xFFFFFFFFu - (unsigned)bidx);

#pragma unroll
    for (int off = 16; off > 0; off >>= 1) {
        unsigned long long o = __shfl_down_sync(0xFFFFFFFFu, key, off);
        key = (o > key) ? o : key;
    }
    __shared__ unsigned long long s_key[NTHREADS / 32];
    __shared__ int s_last;
    __shared__ int s_not64;
    if ((threadIdx.x & 31) == 0) s_key[threadIdx.x >> 5] = key;
    __syncthreads();
    if (threadIdx.x == 0) {
        key = s_key[0];
#pragma unroll
        for (int w = 1; w < NTHREADS / 32; ++w)
            key = (s_key[w] > key) ? s_key[w] : key;
        g_part[blockIdx.x] = key;
        __threadfence();                        // release partial
        unsigned t = atomicAdd(&g_count, 1u);
        s_last = (t == (unsigned)(gridDim.x - 1));
        s_not64 = 0;
    }
    __syncthreads();
    if (!s_last) return;
    __threadfence();                            // acquire all partials

    // ---- rejection-sampling epilogue ----
    // Runtime input dtype detect: first 2048 B of draft exist under either
    // dtype; int64 => every high word is 0 (tokens < 128000).
    const unsigned long long* d64chk = (const unsigned long long*)draft_raw;
    for (int j = threadIdx.x; j < 256; j += NTHREADS)
        if (d64chk[j] >> 32) atomicOr(&s_not64, 1);
    __syncthreads();
    const bool is64 = (s_not64 == 0);

    const int b = threadIdx.x;
    if (b < BATCH) {
        const long long* draft64 = (const long long*)draft_raw;
        const int*       draft32 = (const int*)draft_raw;
        const long long* bonus64 = (const long long*)bonus_raw;
        const int*       bonus32 = (const int*)bonus_raw;

        int tgt[NSPEC];
        bool eq[NSPEC];
        int cum = 0;
#pragma unroll
        for (int s = 0; s < NSPEC; ++s) {
            const int r = b * NSPEC + s;
            unsigned long long k0 = g_part[2 * r];
            unsigned long long k1 = g_part[2 * r + 1];
            unsigned long long km = (k1 > k0) ? k1 : k0;
            tgt[s] = (int)(0xFFFFFFFFu - (unsigned)(km & 0xFFFFFFFFull));
            long long dv = is64 ? draft64[r] : (long long)draft32[r];
            cum += (dv == (long long)tgt[s]) ? 1 : 0;
            eq[s] = ((cum - 1) == s);           // drafts 0..s all matched
        }

        int sum_eq = 0;
#pragma unroll
        for (int s = 0; s < NSPEC; ++s) sum_eq += eq[s] ? 1 : 0;
        const int num_rejected = NSPEC - sum_eq;

        int first_diff = 0;                     // jnp.argmin: first False else 0
        bool any_false = false;
#pragma unroll
        for (int s = 0; s < NSPEC; ++s)
            if (!any_false && !eq[s]) { first_diff = s; any_false = true; }

        float outrow[NSPEC + 1];
        int keep_count = 0;
#pragma unroll
        for (int s = 0; s < NSPEC; ++s) {
            bool keep = (s <= first_diff) || eq[s];
            outrow[s] = keep ? (float)tgt[s] : -1.0f;
            keep_count += keep ? 1 : 0;
        }
        const bool last_all = eq[NSPEC - 1];
        long long bonus = is64 ? bonus64[b] : (long long)bonus32[b];
        outrow[NSPEC] = last_all ? (float)bonus : -1.0f;
        keep_count += last_all ? 1 : 0;

        const float last_tok = outrow[keep_count - 1];

        // Flattened tuple: [64*9 tokens | 64 num_rejected | 64 last_token]
#pragma unroll
        for (int s = 0; s <= NSPEC; ++s)
            out[b * (NSPEC + 1) + s] = outrow[s];
        out[BATCH * (NSPEC + 1) + b]         = (float)num_rejected;
        out[BATCH * (NSPEC + 1) + BATCH + b] = last_tok;
    }

    __syncthreads();
    if (threadIdx.x == 0) g_count = 0;          // reset for next graph replay
}

extern "C" void kernel_launch(void* const* d_in, const int* in_sizes, int n_in,
                              void* d_out, int out_size) {
    const float* logits = (const float*)d_in[0];   // [64, 8, 128000] fp32
    const void*  draft  = d_in[1];                 // [64, 8] int64 or int32
    const void*  bonus  = d_in[2];                 // [64, 1] int64 or int32
    (void)in_sizes; (void)n_in; (void)out_size;

    fused_kernel<<<NPART, NTHREADS>>>(logits, draft, bonus, (float*)d_out);
}